// round 12
// baseline (speedup 1.0000x reference)
#include <cuda_runtime.h>
#include <cuda_fp16.h>
#include <math.h>
#include <stdint.h>

#define B_  2
#define S_  2048
#define D_  2048
#define H_  16
#define HD_ 128
#define M_  (B_*S_)          // 4096
#define N3_ (3*D_)           // 6144
#define K_  D_               // 2048

// ---------------- scratch (device globals; no allocs allowed) ----------------
__device__ __half g_a16[(size_t)M_ * K_];            // GEMM A fp16 (x, then attn out)
__device__ __half g_b16[(size_t)N3_ * K_];           // GEMM B fp16, [N,K]
__device__ __half g_q16[(size_t)(B_*H_) * S_ * HD_];
__device__ __half g_k16[(size_t)(B_*H_) * S_ * HD_];
__device__ __half g_v16[(size_t)(B_*H_) * S_ * HD_];

// ================= helpers =================
__device__ __forceinline__ uint32_t smem_u32(const void* p) {
    uint32_t a;
    asm("{ .reg .u64 t; cvta.to.shared.u64 t, %1; cvt.u32.u64 %0, t; }" : "=r"(a) : "l"(p));
    return a;
}
#define CP_ASYNC16(sm_addr, gptr) \
    asm volatile("cp.async.cg.shared.global [%0], [%1], 16;" :: "r"(sm_addr), "l"(gptr))
#define CP_COMMIT() asm volatile("cp.async.commit_group;" ::: "memory")
#define CP_WAIT1()  asm volatile("cp.async.wait_group 1;" ::: "memory")
#define CP_WAIT2()  asm volatile("cp.async.wait_group 2;" ::: "memory")

#define LDSM_X4(r0, r1, r2, r3, addr) \
    asm volatile("ldmatrix.sync.aligned.m8n8.x4.shared.b16 {%0,%1,%2,%3}, [%4];" \
        : "=r"(r0), "=r"(r1), "=r"(r2), "=r"(r3) : "r"(addr))
#define LDSM_X4_T(r0, r1, r2, r3, addr) \
    asm volatile("ldmatrix.sync.aligned.m8n8.x4.trans.shared.b16 {%0,%1,%2,%3}, [%4];" \
        : "=r"(r0), "=r"(r1), "=r"(r2), "=r"(r3) : "r"(addr))

#define MMAH(d, a, b) \
    asm volatile("mma.sync.aligned.m16n8k16.row.col.f32.f16.f16.f32 " \
        "{%0,%1,%2,%3}, {%4,%5,%6,%7}, {%8,%9}, {%0,%1,%2,%3};" \
        : "+f"((d)[0]), "+f"((d)[1]), "+f"((d)[2]), "+f"((d)[3]) \
        : "r"((a)[0]), "r"((a)[1]), "r"((a)[2]), "r"((a)[3]), "r"((b)[0]), "r"((b)[1]))

__device__ __forceinline__ float ex2f(float x) {
    float y;
    asm("ex2.approx.f32 %0, %1;" : "=f"(y) : "f"(x));
    return y;
}
__device__ __forceinline__ uint32_t pack_h2(float a, float b) {
    __half2 t = __floats2half2_rn(a, b);
    return *(uint32_t*)&t;
}

// ================= fp16 HMMA GEMM common =================
// CTA tile 128x256, 512 threads (16 warps: 4M x 4N), KC=64, 4-stage ring,
// distance-3 prefetch, single __syncthreads per chunk.
#define KC 64
#define GA_STRIDE 144                  // 128 B data + 16 B pad (conflict-free)
#define GA_B (128 * GA_STRIDE)         // 18432
#define GB_B (256 * GA_STRIDE)         // 36864
#define GSTAGE_B (GA_B + GB_B)         // 55296
#define GEMM_NS 4
#define GEMM_SMEM (GEMM_NS * GSTAGE_B) // 221184
#define CS_STRIDE 260                  // fp32 epilogue staging stride

__device__ __forceinline__ void g_load_chunk(
    uint32_t base, const __half* A, const __half* Bt,
    int m0, int n0, int k0, int K, int tid)
{
#pragma unroll
    for (int i = tid; i < 1024; i += 512) {          // A: 128 rows x 8 granules
        int r = i >> 3, g = i & 7;
        CP_ASYNC16(base + (uint32_t)(r * GA_STRIDE + g * 16),
                   A + (size_t)(m0 + r) * K + k0 + g * 8);
    }
#pragma unroll
    for (int i = tid; i < 2048; i += 512) {          // B: 256 rows x 8 granules
        int r = i >> 3, g = i & 7;
        CP_ASYNC16(base + GA_B + (uint32_t)(r * GA_STRIDE + g * 16),
                   Bt + (size_t)(n0 + r) * K + k0 + g * 8);
    }
}

// mainloop shared by both GEMMs; leaves accumulators in acc[2][8][4]
__device__ __forceinline__ void gemm_mainloop(
    uint32_t smb, const __half* A, const __half* Bt,
    int m0, int n0, int K, int tid, int wm, int wn, int lane,
    float acc[2][8][4])
{
#pragma unroll
    for (int i = 0; i < 2; i++)
#pragma unroll
        for (int j = 0; j < 8; j++)
#pragma unroll
            for (int t = 0; t < 4; t++) acc[i][j][t] = 0.f;

    g_load_chunk(smb,                A, Bt, m0, n0, 0,      K, tid);
    CP_COMMIT();
    g_load_chunk(smb + GSTAGE_B,     A, Bt, m0, n0, KC,     K, tid);
    CP_COMMIT();
    g_load_chunk(smb + 2 * GSTAGE_B, A, Bt, m0, n0, 2 * KC, K, tid);
    CP_COMMIT();

    const int NC = K / KC;
    const int lrow = lane & 15;
    const int lcol = (lane >> 4) * 16;

    int stage = 0;
    for (int c = 0; c < NC; c++) {
        CP_WAIT2();                    // chunk c done (c+1, c+2 may be in flight)
        __syncthreads();               // all warps finished chunk c-1 compute

        // issue chunk c+3 into the stage chunk c-1 just vacated
        if (c + 3 < NC) {
            int ns = stage + 3; if (ns >= GEMM_NS) ns -= GEMM_NS;
            g_load_chunk(smb + (uint32_t)ns * GSTAGE_B, A, Bt, m0, n0, (c + 3) * KC, K, tid);
        }
        CP_COMMIT();

        const uint32_t base = smb + (uint32_t)stage * GSTAGE_B;
#pragma unroll
        for (int ks = 0; ks < 4; ks++) {
            uint32_t a[2][4], b[8][2];
#pragma unroll
            for (int mt = 0; mt < 2; mt++) {
                uint32_t addr = base +
                    (uint32_t)((wm * 32 + mt * 16 + lrow) * GA_STRIDE + ks * 32 + lcol);
                LDSM_X4(a[mt][0], a[mt][1], a[mt][2], a[mt][3], addr);
            }
#pragma unroll
            for (int nb = 0; nb < 4; nb++) {
                uint32_t r0, r1, r2, r3;
                uint32_t addr = base + GA_B +
                    (uint32_t)((wn * 64 + nb * 16 + lrow) * GA_STRIDE + ks * 32 + lcol);
                LDSM_X4(r0, r1, r2, r3, addr);
                b[2 * nb][0] = r0; b[2 * nb][1] = r2;
                b[2 * nb + 1][0] = r1; b[2 * nb + 1][1] = r3;
            }
#pragma unroll
            for (int mt = 0; mt < 2; mt++)
#pragma unroll
                for (int nt = 0; nt < 8; nt++)
                    MMAH(acc[mt][nt], a[mt], b[nt]);
        }
        if (++stage == GEMM_NS) stage = 0;
    }
}

// ---------- generic GEMM (fp32 out) for the output projection ----------
__global__ __launch_bounds__(512)
void gemm_h(const __half* __restrict__ A, const __half* __restrict__ Bt,
            float* __restrict__ C, int N, int K)
{
    extern __shared__ char sm[];
    const uint32_t smb = smem_u32(sm);
    const int tid  = threadIdx.x;
    const int wid  = tid >> 5;
    const int lane = tid & 31;
    const int wm = wid & 3;
    const int wn = wid >> 2;
    const int m0 = blockIdx.y * 128;
    const int n0 = blockIdx.x * 256;

    float acc[2][8][4];
    gemm_mainloop(smb, A, Bt, m0, n0, K, tid, wm, wn, lane, acc);

    const int grow = lane >> 2;
    const int gcol = (lane & 3) * 2;
#pragma unroll
    for (int mt = 0; mt < 2; mt++) {
        int row = m0 + wm * 32 + mt * 16 + grow;
#pragma unroll
        for (int nt = 0; nt < 8; nt++) {
            int col = n0 + wn * 64 + nt * 8 + gcol;
            float* c0 = C + (size_t)row * N + col;
            float* c1 = C + (size_t)(row + 8) * N + col;
            c0[0] = acc[mt][nt][0]; c0[1] = acc[mt][nt][1];
            c1[0] = acc[mt][nt][2]; c1[1] = acc[mt][nt][3];
        }
    }
}

// ---------- QKV GEMM with fused RoPE + fp16 scatter epilogue ----------
#define QSCALE 0.1275174329213838f    // log2e / sqrt(128)

__global__ __launch_bounds__(512)
void gemm_qkv(const __half* __restrict__ A, const __half* __restrict__ Bt,
              const float* __restrict__ sinp, const float* __restrict__ cosp,
              __half* __restrict__ Qo, __half* __restrict__ Ko, __half* __restrict__ Vo)
{
    extern __shared__ char sm[];
    const uint32_t smb = smem_u32(sm);
    const int tid  = threadIdx.x;
    const int wid  = tid >> 5;
    const int lane = tid & 31;
    const int wm = wid & 3;
    const int wn = wid >> 2;
    const int m0 = blockIdx.y * 128;
    const int n0 = blockIdx.x * 256;

    float acc[2][8][4];
    gemm_mainloop(smb, A, Bt, m0, n0, K_, tid, wm, wn, lane, acc);

    // ---- stage fp32 accs in smem (pipeline stages are retired) ----
    __syncthreads();
    float* cs = (float*)sm;
    const int grow = lane >> 2;
    const int gcol = (lane & 3) * 2;
#pragma unroll
    for (int mt = 0; mt < 2; mt++) {
        int r = wm * 32 + mt * 16 + grow;
#pragma unroll
        for (int nt = 0; nt < 8; nt++) {
            int col = wn * 64 + nt * 8 + gcol;
            cs[r * CS_STRIDE + col]       = acc[mt][nt][0];
            cs[r * CS_STRIDE + col + 1]   = acc[mt][nt][1];
            cs[(r + 8) * CS_STRIDE + col]     = acc[mt][nt][2];
            cs[(r + 8) * CS_STRIDE + col + 1] = acc[mt][nt][3];
        }
    }
    __syncthreads();

    // ---- RoPE + fp16 + head-major scatter ----
    const int which = n0 >> 11;            // 0=q, 1=k, 2=v
    const int h0 = (n0 & 2047) >> 7;       // first head in tile

    for (int it = tid; it < 128 * 64; it += 512) {
        int r  = it >> 6;                  // tile row 0..127
        int qd = (it & 63) << 2;           // tile col quad 0..252
        int hh = qd >> 7;                  // head-in-tile 0/1
        int hd = qd & 127;                 // headdim pos (multiple of 4)
        int m = m0 + r;
        int b = m >> 11, s = m & 2047;

        float4 v = *(float4*)&cs[r * CS_STRIDE + qd];
        float out0, out1, out2, out3;

        if (which == 2) {
            out0 = v.x; out1 = v.y; out2 = v.z; out3 = v.w;
        } else {
            float4 c4 = *(const float4*)&cosp[s * HD_ + hd];
            float4 s4 = *(const float4*)&sinp[s * HD_ + hd];
            float4 rv;
            if (hd < 64) {
                float4 t = *(float4*)&cs[r * CS_STRIDE + qd + 64];
                rv.x = -t.x; rv.y = -t.y; rv.z = -t.z; rv.w = -t.w;
            } else {
                rv = *(float4*)&cs[r * CS_STRIDE + qd - 64];
            }
            out0 = v.x * c4.x + rv.x * s4.x;
            out1 = v.y * c4.y + rv.y * s4.y;
            out2 = v.z * c4.z + rv.z * s4.z;
            out3 = v.w * c4.w + rv.w * s4.w;
            if (which == 0) {
                out0 *= QSCALE; out1 *= QSCALE; out2 *= QSCALE; out3 *= QSCALE;
            }
        }
        __half* dst = (which == 0) ? Qo : (which == 1) ? Ko : Vo;
        size_t ob = (((size_t)(b * H_ + h0 + hh)) * S_ + s) * HD_ + hd;
        uint2 pk;
        pk.x = pack_h2(out0, out1);
        pk.y = pack_h2(out2, out3);
        *(uint2*)(dst + ob) = pk;
    }
}

// ================= conversion kernels =================
__global__ __launch_bounds__(256)
void conv16(const float* __restrict__ A, __half* __restrict__ out, int n4)
{
    int i = blockIdx.x * blockDim.x + threadIdx.x;
    if (i >= n4) return;
    float4 v = ((const float4*)A)[i];
    uint2 r;
    r.x = pack_h2(v.x, v.y);
    r.y = pack_h2(v.z, v.w);
    ((uint2*)out)[i] = r;
}

// W[K,N] fp32 -> Bt[N,K] fp16 transpose, 32x32 tiles
__global__ __launch_bounds__(256)
void conv_w_t16(const float* __restrict__ W, __half* __restrict__ out, int K, int N)
{
    __shared__ float t[32][33];
    const int tx = threadIdx.x & 31;
    const int ty = threadIdx.x >> 5;
    const int n0 = blockIdx.x * 32;
    const int k0 = blockIdx.y * 32;
#pragma unroll
    for (int j = 0; j < 4; j++)
        t[ty + j * 8][tx] = W[(size_t)(k0 + ty + j * 8) * N + n0 + tx];
    __syncthreads();
#pragma unroll
    for (int j = 0; j < 4; j++) {
        int r = ty + j * 8;
        out[(size_t)(n0 + r) * K + k0 + tx] = __float2half(t[tx][r]);
    }
}

// ---------------- fp16 HMMA flash attention: BM=128, BN=64, HD=128 ----------------
// Q tile staged in smem (frees 32 regs -> 2 CTAs/SM), 2-stage KV ring.
#define AT_STRIDE 272                 // 256 B data + 16 B pad
#define KT_B (64 * AT_STRIDE)         // 17408
#define V_OFF KT_B
#define STAGE_AT (2 * KT_B)           // 34816
#define ATQ_B (128 * AT_STRIDE)       // 34816 (Q tile)
#define ATTN_SMEM (ATQ_B + 2 * STAGE_AT)  // 104448 -> 2 CTAs/SM

__device__ __forceinline__ void load_kv_tile(
    uint32_t base, const __half* Kp, const __half* Vp, int bh, int kt, int tid)
{
    size_t gb = ((size_t)bh * S_ + (size_t)kt * 64) * HD_;
#pragma unroll
    for (int i = tid; i < 1024; i += 256) {
        int r = i >> 4, g = i & 15;
        uint32_t so = (uint32_t)(r * AT_STRIDE + g * 16);
        size_t go = gb + (size_t)r * HD_ + g * 8;
        CP_ASYNC16(base + so,        Kp + go);
        CP_ASYNC16(base + V_OFF + so, Vp + go);
    }
}

__global__ __launch_bounds__(256, 2)
void attn_h(const __half* __restrict__ Qp, const __half* __restrict__ Kp,
            const __half* __restrict__ Vp, __half* __restrict__ Oa)
{
    extern __shared__ char sm[];
    const uint32_t smb = smem_u32(sm);
    const int tid  = threadIdx.x;
    const int wid  = tid >> 5;
    const int lane = tid & 31;
    const int grow = lane >> 2;
    const int gcol2 = (lane & 3) * 2;
    const int bh = blockIdx.y;
    const int iq = gridDim.x - 1 - blockIdx.x;      // heavy tiles first
    const int row0 = iq * 128 + wid * 16;

    const uint32_t stg0 = smb + ATQ_B;
    const uint32_t stg1 = smb + ATQ_B + STAGE_AT;

    // ---- prologue: Q tile + kv0 (group 0), kv1 (group 1) ----
    {
        size_t qg = ((size_t)bh * S_ + (size_t)iq * 128) * HD_;
#pragma unroll
        for (int i = tid; i < 2048; i += 256) {
            int r = i >> 4, g = i & 15;
            CP_ASYNC16(smb + (uint32_t)(r * AT_STRIDE + g * 16),
                       Qp + qg + (size_t)r * HD_ + g * 8);
        }
    }
    load_kv_tile(stg0, Kp, Vp, bh, 0, tid);
    CP_COMMIT();
    const int ktmax = 2 * iq + 1;
    if (ktmax >= 1) load_kv_tile(stg1, Kp, Vp, bh, 1, tid);
    CP_COMMIT();

    float o[16][4];
#pragma unroll
    for (int i = 0; i < 16; i++)
#pragma unroll
        for (int j = 0; j < 4; j++) o[i][j] = 0.f;
    float m0 = -1e30f, m1 = -1e30f, l0 = 0.f, l1 = 0.f;

    const int lrow = lane & 15;
    const int lcol = (lane >> 4) * 16;
    const uint32_t qbase = smb + (uint32_t)((wid * 16 + lrow) * AT_STRIDE + lcol);

    for (int kt = 0; kt <= ktmax; kt++) {
        CP_WAIT1();
        __syncthreads();
        const uint32_t stg = (kt & 1) ? stg1 : stg0;
        const bool active = (kt * 64 <= row0 + 15);

        if (active) {
            // ---- S = Q K^T  (Q fragments re-fetched from smem per ks) ----
            float s[8][4];
#pragma unroll
            for (int i = 0; i < 8; i++)
#pragma unroll
                for (int j = 0; j < 4; j++) s[i][j] = 0.f;

#pragma unroll
            for (int ks = 0; ks < 8; ks++) {
                uint32_t a[4];
                LDSM_X4(a[0], a[1], a[2], a[3], qbase + (uint32_t)(ks * 32));
                uint32_t b[8][2];
#pragma unroll
                for (int nb = 0; nb < 4; nb++) {
                    uint32_t r0, r1, r2, r3;
                    uint32_t addr = stg +
                        (uint32_t)((nb * 16 + lrow) * AT_STRIDE + ks * 32 + lcol);
                    LDSM_X4(r0, r1, r2, r3, addr);
                    b[2 * nb][0] = r0; b[2 * nb][1] = r2;
                    b[2 * nb + 1][0] = r1; b[2 * nb + 1][1] = r3;
                }
#pragma unroll
                for (int nt = 0; nt < 8; nt++) MMAH(s[nt], a, b[nt]);
            }

            // ---- causal mask ----
            if (kt * 64 + 63 > row0) {
                const int kb = kt * 64;
#pragma unroll
                for (int nt = 0; nt < 8; nt++) {
#pragma unroll
                    for (int e = 0; e < 4; e++) {
                        int col = kb + nt * 8 + gcol2 + (e & 1);
                        int row = row0 + grow + ((e >> 1) << 3);
                        if (col > row) s[nt][e] = -1e30f;
                    }
                }
            }

            // ---- online softmax (log2 domain) ----
            float ml0 = -1e30f, ml1 = -1e30f;
#pragma unroll
            for (int nt = 0; nt < 8; nt++) {
                ml0 = fmaxf(ml0, fmaxf(s[nt][0], s[nt][1]));
                ml1 = fmaxf(ml1, fmaxf(s[nt][2], s[nt][3]));
            }
#pragma unroll
            for (int d = 1; d < 4; d <<= 1) {
                ml0 = fmaxf(ml0, __shfl_xor_sync(0xFFFFFFFFu, ml0, d));
                ml1 = fmaxf(ml1, __shfl_xor_sync(0xFFFFFFFFu, ml1, d));
            }
            float mn0 = fmaxf(m0, ml0), mn1 = fmaxf(m1, ml1);
            float sc0 = ex2f(m0 - mn0), sc1 = ex2f(m1 - mn1);
            float sum0 = 0.f, sum1 = 0.f;
#pragma unroll
            for (int nt = 0; nt < 8; nt++) {
                s[nt][0] = ex2f(s[nt][0] - mn0);
                s[nt][1] = ex2f(s[nt][1] - mn0);
                s[nt][2] = ex2f(s[nt][2] - mn1);
                s[nt][3] = ex2f(s[nt][3] - mn1);
                sum0 += s[nt][0] + s[nt][1];
                sum1 += s[nt][2] + s[nt][3];
            }
#pragma unroll
            for (int d = 1; d < 4; d <<= 1) {
                sum0 += __shfl_xor_sync(0xFFFFFFFFu, sum0, d);
                sum1 += __shfl_xor_sync(0xFFFFFFFFu, sum1, d);
            }
            l0 = l0 * sc0 + sum0;
            l1 = l1 * sc1 + sum1;
            m0 = mn0; m1 = mn1;
#pragma unroll
            for (int nt = 0; nt < 16; nt++) {
                o[nt][0] *= sc0; o[nt][1] *= sc0;
                o[nt][2] *= sc1; o[nt][3] *= sc1;
            }

            // ---- pack P into fp16 A-fragments ----
            uint32_t pa[4][4];
#pragma unroll
            for (int j = 0; j < 4; j++) {
                pa[j][0] = pack_h2(s[2*j][0],   s[2*j][1]);
                pa[j][1] = pack_h2(s[2*j][2],   s[2*j][3]);
                pa[j][2] = pack_h2(s[2*j+1][0], s[2*j+1][1]);
                pa[j][3] = pack_h2(s[2*j+1][2], s[2*j+1][3]);
            }

            // ---- O += P V ----
#pragma unroll
            for (int ks4 = 0; ks4 < 4; ks4++) {
#pragma unroll
                for (int np = 0; np < 8; np++) {
                    uint32_t r0, r1, r2, r3;
                    uint32_t addr = stg + V_OFF +
                        (uint32_t)((ks4 * 16 + lrow) * AT_STRIDE + np * 32 + lcol);
                    LDSM_X4_T(r0, r1, r2, r3, addr);
                    uint32_t b0[2] = { r0, r1 }, b1[2] = { r2, r3 };
                    MMAH(o[2 * np],     pa[ks4], b0);
                    MMAH(o[2 * np + 1], pa[ks4], b1);
                }
            }
        }

        __syncthreads();               // compute done before stage reuse
        if (kt + 2 <= ktmax)
            load_kv_tile((kt & 1) ? stg1 : stg0, Kp, Vp, bh, kt + 2, tid);
        CP_COMMIT();
    }

    // ---- epilogue: write fp16 directly into proj-GEMM A buffer ----
    const int b = bh >> 4, h = bh & 15;
    float inv0 = 1.f / l0, inv1 = 1.f / l1;
#pragma unroll
    for (int nt = 0; nt < 16; nt++) {
        int col = h * HD_ + nt * 8 + gcol2;
        __half* p0 = Oa + ((size_t)(b * S_ + row0 + grow)) * D_ + col;
        __half* p1 = Oa + ((size_t)(b * S_ + row0 + grow + 8)) * D_ + col;
        *(uint32_t*)p0 = pack_h2(o[nt][0] * inv0, o[nt][1] * inv0);
        *(uint32_t*)p1 = pack_h2(o[nt][2] * inv1, o[nt][3] * inv1);
    }
}

// ---------------- launch ----------------
extern "C" void kernel_launch(void* const* d_in, const int* in_sizes, int n_in,
                              void* d_out, int out_size)
{
    const float* x     = (const float*)d_in[0];
    // d_in[1] = mask (causal tril, handled analytically)
    const float* sinp  = (const float*)d_in[2];
    const float* cosp  = (const float*)d_in[3];
    const float* Wqkv  = (const float*)d_in[4];
    const float* Wproj = (const float*)d_in[5];
    float* out = (float*)d_out;

    __half *a16, *b16, *q16, *k16, *v16;
    cudaGetSymbolAddress((void**)&a16, g_a16);
    cudaGetSymbolAddress((void**)&b16, g_b16);
    cudaGetSymbolAddress((void**)&q16, g_q16);
    cudaGetSymbolAddress((void**)&k16, g_k16);
    cudaGetSymbolAddress((void**)&v16, g_v16);

    cudaFuncSetAttribute(gemm_h,   cudaFuncAttributeMaxDynamicSharedMemorySize, GEMM_SMEM);
    cudaFuncSetAttribute(gemm_qkv, cudaFuncAttributeMaxDynamicSharedMemorySize, GEMM_SMEM);
    cudaFuncSetAttribute(attn_h,   cudaFuncAttributeMaxDynamicSharedMemorySize, ATTN_SMEM);

    // 1) convert x and Wqkv to fp16
    conv16<<<(M_ * K_ / 4 + 255) / 256, 256>>>(x, a16, M_ * K_ / 4);
    conv_w_t16<<<dim3(N3_ / 32, K_ / 32), 256>>>(Wqkv, b16, K_, N3_);

    // 2) QKV projection + fused RoPE + head-major fp16 scatter
    gemm_qkv<<<dim3(N3_ / 256, M_ / 128), 512, GEMM_SMEM>>>(a16, b16, sinp, cosp,
                                                            q16, k16, v16);

    // 3) causal flash attention (tensor cores); writes proj A operand fp16
    attn_h<<<dim3(S_ / 128, B_ * H_), 256, ATTN_SMEM>>>(q16, k16, v16, a16);

    // 4) output projection (tensor cores)
    conv_w_t16<<<dim3(D_ / 32, K_ / 32), 256>>>(Wproj, b16, K_, D_);
    gemm_h<<<dim3(D_ / 256, M_ / 128), 512, GEMM_SMEM>>>(a16, b16, out, D_, K_);
}

// round 13
// speedup vs baseline: 1.0204x; 1.0204x over previous
#include <cuda_runtime.h>
#include <cuda_fp16.h>
#include <math.h>
#include <stdint.h>

#define B_  2
#define S_  2048
#define D_  2048
#define H_  16
#define HD_ 128
#define M_  (B_*S_)          // 4096
#define N3_ (3*D_)           // 6144
#define K_  D_               // 2048

// ---------------- scratch (device globals; no allocs allowed) ----------------
__device__ __half g_a16[(size_t)M_ * K_];            // GEMM A fp16 (x, then attn out)
__device__ __half g_b16[(size_t)N3_ * K_];           // GEMM B fp16, [N,K]
__device__ __half g_q16[(size_t)(B_*H_) * S_ * HD_];
__device__ __half g_k16[(size_t)(B_*H_) * S_ * HD_];
__device__ __half g_v16[(size_t)(B_*H_) * S_ * HD_];

// ================= helpers =================
__device__ __forceinline__ uint32_t smem_u32(const void* p) {
    uint32_t a;
    asm("{ .reg .u64 t; cvta.to.shared.u64 t, %1; cvt.u32.u64 %0, t; }" : "=r"(a) : "l"(p));
    return a;
}
#define CP_ASYNC16(sm_addr, gptr) \
    asm volatile("cp.async.cg.shared.global [%0], [%1], 16;" :: "r"(sm_addr), "l"(gptr))
#define CP_COMMIT() asm volatile("cp.async.commit_group;" ::: "memory")
#define CP_WAIT1()  asm volatile("cp.async.wait_group 1;" ::: "memory")
#define CP_WAIT2()  asm volatile("cp.async.wait_group 2;" ::: "memory")

#define LDSM_X4(r0, r1, r2, r3, addr) \
    asm volatile("ldmatrix.sync.aligned.m8n8.x4.shared.b16 {%0,%1,%2,%3}, [%4];" \
        : "=r"(r0), "=r"(r1), "=r"(r2), "=r"(r3) : "r"(addr))
#define LDSM_X4_T(r0, r1, r2, r3, addr) \
    asm volatile("ldmatrix.sync.aligned.m8n8.x4.trans.shared.b16 {%0,%1,%2,%3}, [%4];" \
        : "=r"(r0), "=r"(r1), "=r"(r2), "=r"(r3) : "r"(addr))

#define MMAH(d, a, b) \
    asm volatile("mma.sync.aligned.m16n8k16.row.col.f32.f16.f16.f32 " \
        "{%0,%1,%2,%3}, {%4,%5,%6,%7}, {%8,%9}, {%0,%1,%2,%3};" \
        : "+f"((d)[0]), "+f"((d)[1]), "+f"((d)[2]), "+f"((d)[3]) \
        : "r"((a)[0]), "r"((a)[1]), "r"((a)[2]), "r"((a)[3]), "r"((b)[0]), "r"((b)[1]))

__device__ __forceinline__ float ex2f(float x) {
    float y;
    asm("ex2.approx.f32 %0, %1;" : "=f"(y) : "f"(x));
    return y;
}
__device__ __forceinline__ uint32_t pack_h2(float a, float b) {
    __half2 t = __floats2half2_rn(a, b);
    return *(uint32_t*)&t;
}

// ================= fp16 HMMA GEMM common =================
// CTA tile 128x256, 512 threads (16 warps: 4M x 4N), KC=64, 4-stage ring,
// distance-3 prefetch, single __syncthreads per chunk.
#define KC 64
#define GA_STRIDE 144                  // 128 B data + 16 B pad (conflict-free)
#define GA_B (128 * GA_STRIDE)         // 18432
#define GB_B (256 * GA_STRIDE)         // 36864
#define GSTAGE_B (GA_B + GB_B)         // 55296
#define GEMM_NS 4
#define GEMM_SMEM (GEMM_NS * GSTAGE_B) // 221184
#define CS_STRIDE 260                  // fp32 epilogue staging stride

__device__ __forceinline__ void g_load_chunk(
    uint32_t base, const __half* A, const __half* Bt,
    int m0, int n0, int k0, int K, int tid)
{
#pragma unroll
    for (int i = tid; i < 1024; i += 512) {          // A: 128 rows x 8 granules
        int r = i >> 3, g = i & 7;
        CP_ASYNC16(base + (uint32_t)(r * GA_STRIDE + g * 16),
                   A + (size_t)(m0 + r) * K + k0 + g * 8);
    }
#pragma unroll
    for (int i = tid; i < 2048; i += 512) {          // B: 256 rows x 8 granules
        int r = i >> 3, g = i & 7;
        CP_ASYNC16(base + GA_B + (uint32_t)(r * GA_STRIDE + g * 16),
                   Bt + (size_t)(n0 + r) * K + k0 + g * 8);
    }
}

// mainloop shared by both GEMMs; leaves accumulators in acc[2][8][4]
__device__ __forceinline__ void gemm_mainloop(
    uint32_t smb, const __half* A, const __half* Bt,
    int m0, int n0, int K, int tid, int wm, int wn, int lane,
    float acc[2][8][4])
{
#pragma unroll
    for (int i = 0; i < 2; i++)
#pragma unroll
        for (int j = 0; j < 8; j++)
#pragma unroll
            for (int t = 0; t < 4; t++) acc[i][j][t] = 0.f;

    g_load_chunk(smb,                A, Bt, m0, n0, 0,      K, tid);
    CP_COMMIT();
    g_load_chunk(smb + GSTAGE_B,     A, Bt, m0, n0, KC,     K, tid);
    CP_COMMIT();
    g_load_chunk(smb + 2 * GSTAGE_B, A, Bt, m0, n0, 2 * KC, K, tid);
    CP_COMMIT();

    const int NC = K / KC;
    const int lrow = lane & 15;
    const int lcol = (lane >> 4) * 16;

    int stage = 0;
    for (int c = 0; c < NC; c++) {
        CP_WAIT2();                    // chunk c done (c+1, c+2 may be in flight)
        __syncthreads();               // all warps finished chunk c-1 compute

        // issue chunk c+3 into the stage chunk c-1 just vacated
        if (c + 3 < NC) {
            int ns = stage + 3; if (ns >= GEMM_NS) ns -= GEMM_NS;
            g_load_chunk(smb + (uint32_t)ns * GSTAGE_B, A, Bt, m0, n0, (c + 3) * KC, K, tid);
        }
        CP_COMMIT();

        const uint32_t base = smb + (uint32_t)stage * GSTAGE_B;
#pragma unroll
        for (int ks = 0; ks < 4; ks++) {
            uint32_t a[2][4], b[8][2];
#pragma unroll
            for (int mt = 0; mt < 2; mt++) {
                uint32_t addr = base +
                    (uint32_t)((wm * 32 + mt * 16 + lrow) * GA_STRIDE + ks * 32 + lcol);
                LDSM_X4(a[mt][0], a[mt][1], a[mt][2], a[mt][3], addr);
            }
#pragma unroll
            for (int nb = 0; nb < 4; nb++) {
                uint32_t r0, r1, r2, r3;
                uint32_t addr = base + GA_B +
                    (uint32_t)((wn * 64 + nb * 16 + lrow) * GA_STRIDE + ks * 32 + lcol);
                LDSM_X4(r0, r1, r2, r3, addr);
                b[2 * nb][0] = r0; b[2 * nb][1] = r2;
                b[2 * nb + 1][0] = r1; b[2 * nb + 1][1] = r3;
            }
#pragma unroll
            for (int mt = 0; mt < 2; mt++)
#pragma unroll
                for (int nt = 0; nt < 8; nt++)
                    MMAH(acc[mt][nt], a[mt], b[nt]);
        }
        if (++stage == GEMM_NS) stage = 0;
    }
}

// ---------- generic GEMM (fp32 out) for the output projection ----------
__global__ __launch_bounds__(512)
void gemm_h(const __half* __restrict__ A, const __half* __restrict__ Bt,
            float* __restrict__ C, int N, int K)
{
    extern __shared__ char sm[];
    const uint32_t smb = smem_u32(sm);
    const int tid  = threadIdx.x;
    const int wid  = tid >> 5;
    const int lane = tid & 31;
    const int wm = wid & 3;
    const int wn = wid >> 2;
    const int m0 = blockIdx.y * 128;
    const int n0 = blockIdx.x * 256;

    float acc[2][8][4];
    gemm_mainloop(smb, A, Bt, m0, n0, K, tid, wm, wn, lane, acc);

    const int grow = lane >> 2;
    const int gcol = (lane & 3) * 2;
#pragma unroll
    for (int mt = 0; mt < 2; mt++) {
        int row = m0 + wm * 32 + mt * 16 + grow;
#pragma unroll
        for (int nt = 0; nt < 8; nt++) {
            int col = n0 + wn * 64 + nt * 8 + gcol;
            float* c0 = C + (size_t)row * N + col;
            float* c1 = C + (size_t)(row + 8) * N + col;
            c0[0] = acc[mt][nt][0]; c0[1] = acc[mt][nt][1];
            c1[0] = acc[mt][nt][2]; c1[1] = acc[mt][nt][3];
        }
    }
}

// ---------- QKV GEMM with fused RoPE + fp16 scatter epilogue ----------
#define QSCALE 0.1275174329213838f    // log2e / sqrt(128)

__global__ __launch_bounds__(512)
void gemm_qkv(const __half* __restrict__ A, const __half* __restrict__ Bt,
              const float* __restrict__ sinp, const float* __restrict__ cosp,
              __half* __restrict__ Qo, __half* __restrict__ Ko, __half* __restrict__ Vo)
{
    extern __shared__ char sm[];
    const uint32_t smb = smem_u32(sm);
    const int tid  = threadIdx.x;
    const int wid  = tid >> 5;
    const int lane = tid & 31;
    const int wm = wid & 3;
    const int wn = wid >> 2;
    const int m0 = blockIdx.y * 128;
    const int n0 = blockIdx.x * 256;

    float acc[2][8][4];
    gemm_mainloop(smb, A, Bt, m0, n0, K_, tid, wm, wn, lane, acc);

    // ---- stage fp32 accs in smem (pipeline stages are retired) ----
    __syncthreads();
    float* cs = (float*)sm;
    const int grow = lane >> 2;
    const int gcol = (lane & 3) * 2;
#pragma unroll
    for (int mt = 0; mt < 2; mt++) {
        int r = wm * 32 + mt * 16 + grow;
#pragma unroll
        for (int nt = 0; nt < 8; nt++) {
            int col = wn * 64 + nt * 8 + gcol;
            cs[r * CS_STRIDE + col]       = acc[mt][nt][0];
            cs[r * CS_STRIDE + col + 1]   = acc[mt][nt][1];
            cs[(r + 8) * CS_STRIDE + col]     = acc[mt][nt][2];
            cs[(r + 8) * CS_STRIDE + col + 1] = acc[mt][nt][3];
        }
    }
    __syncthreads();

    // ---- RoPE + fp16 + head-major scatter ----
    const int which = n0 >> 11;            // 0=q, 1=k, 2=v
    const int h0 = (n0 & 2047) >> 7;       // first head in tile

    for (int it = tid; it < 128 * 64; it += 512) {
        int r  = it >> 6;                  // tile row 0..127
        int qd = (it & 63) << 2;           // tile col quad 0..252
        int hh = qd >> 7;                  // head-in-tile 0/1
        int hd = qd & 127;                 // headdim pos (multiple of 4)
        int m = m0 + r;
        int b = m >> 11, s = m & 2047;

        float4 v = *(float4*)&cs[r * CS_STRIDE + qd];
        float out0, out1, out2, out3;

        if (which == 2) {
            out0 = v.x; out1 = v.y; out2 = v.z; out3 = v.w;
        } else {
            float4 c4 = *(const float4*)&cosp[s * HD_ + hd];
            float4 s4 = *(const float4*)&sinp[s * HD_ + hd];
            float4 rv;
            if (hd < 64) {
                float4 t = *(float4*)&cs[r * CS_STRIDE + qd + 64];
                rv.x = -t.x; rv.y = -t.y; rv.z = -t.z; rv.w = -t.w;
            } else {
                rv = *(float4*)&cs[r * CS_STRIDE + qd - 64];
            }
            out0 = v.x * c4.x + rv.x * s4.x;
            out1 = v.y * c4.y + rv.y * s4.y;
            out2 = v.z * c4.z + rv.z * s4.z;
            out3 = v.w * c4.w + rv.w * s4.w;
            if (which == 0) {
                out0 *= QSCALE; out1 *= QSCALE; out2 *= QSCALE; out3 *= QSCALE;
            }
        }
        __half* dst = (which == 0) ? Qo : (which == 1) ? Ko : Vo;
        size_t ob = (((size_t)(b * H_ + h0 + hh)) * S_ + s) * HD_ + hd;
        uint2 pk;
        pk.x = pack_h2(out0, out1);
        pk.y = pack_h2(out2, out3);
        *(uint2*)(dst + ob) = pk;
    }
}

// ================= conversion kernels =================
__global__ __launch_bounds__(256)
void conv16(const float* __restrict__ A, __half* __restrict__ out, int n4)
{
    int i = blockIdx.x * blockDim.x + threadIdx.x;
    if (i >= n4) return;
    float4 v = ((const float4*)A)[i];
    uint2 r;
    r.x = pack_h2(v.x, v.y);
    r.y = pack_h2(v.z, v.w);
    ((uint2*)out)[i] = r;
}

// W[K,N] fp32 -> Bt[N,K] fp16 transpose, 32x32 tiles
__global__ __launch_bounds__(256)
void conv_w_t16(const float* __restrict__ W, __half* __restrict__ out, int K, int N)
{
    __shared__ float t[32][33];
    const int tx = threadIdx.x & 31;
    const int ty = threadIdx.x >> 5;
    const int n0 = blockIdx.x * 32;
    const int k0 = blockIdx.y * 32;
#pragma unroll
    for (int j = 0; j < 4; j++)
        t[ty + j * 8][tx] = W[(size_t)(k0 + ty + j * 8) * N + n0 + tx];
    __syncthreads();
#pragma unroll
    for (int j = 0; j < 4; j++) {
        int r = ty + j * 8;
        out[(size_t)(n0 + r) * K + k0 + tx] = __float2half(t[tx][r]);
    }
}

// ---------------- fp16 HMMA flash attention ----------------
// BM=128, 4 warps (128 threads), warp tile = 32 q-rows x 64 keys (2 m-frags),
// Q staged in smem, 2-stage KV ring, 2 CTAs/SM.
#define AT_STRIDE 272                 // 256 B data + 16 B pad
#define KT_B (64 * AT_STRIDE)         // 17408
#define V_OFF KT_B
#define STAGE_AT (2 * KT_B)           // 34816
#define ATQ_B (128 * AT_STRIDE)       // 34816 (Q tile)
#define ATTN_SMEM (ATQ_B + 2 * STAGE_AT)  // 104448 -> 2 CTAs/SM

__device__ __forceinline__ void load_kv_tile(
    uint32_t base, const __half* Kp, const __half* Vp, int bh, int kt, int tid)
{
    size_t gb = ((size_t)bh * S_ + (size_t)kt * 64) * HD_;
#pragma unroll
    for (int i = tid; i < 1024; i += 128) {
        int r = i >> 4, g = i & 15;
        uint32_t so = (uint32_t)(r * AT_STRIDE + g * 16);
        size_t go = gb + (size_t)r * HD_ + g * 8;
        CP_ASYNC16(base + so,         Kp + go);
        CP_ASYNC16(base + V_OFF + so, Vp + go);
    }
}

__global__ __launch_bounds__(128, 2)
void attn_h(const __half* __restrict__ Qp, const __half* __restrict__ Kp,
            const __half* __restrict__ Vp, __half* __restrict__ Oa)
{
    extern __shared__ char sm[];
    const uint32_t smb = smem_u32(sm);
    const int tid  = threadIdx.x;
    const int wid  = tid >> 5;          // 0..3
    const int lane = tid & 31;
    const int grow = lane >> 2;
    const int gcol2 = (lane & 3) * 2;
    const int bh = blockIdx.y;
    const int iq = gridDim.x - 1 - blockIdx.x;      // heavy tiles first
    const int row0 = iq * 128 + wid * 32;           // warp covers rows [row0, row0+32)

    const uint32_t stg0 = smb + ATQ_B;
    const uint32_t stg1 = smb + ATQ_B + STAGE_AT;

    // ---- prologue: Q tile + kv0 (group 0), kv1 (group 1) ----
    {
        size_t qg = ((size_t)bh * S_ + (size_t)iq * 128) * HD_;
#pragma unroll
        for (int i = tid; i < 2048; i += 128) {
            int r = i >> 4, g = i & 15;
            CP_ASYNC16(smb + (uint32_t)(r * AT_STRIDE + g * 16),
                       Qp + qg + (size_t)r * HD_ + g * 8);
        }
    }
    load_kv_tile(stg0, Kp, Vp, bh, 0, tid);
    CP_COMMIT();
    const int ktmax = 2 * iq + 1;
    if (ktmax >= 1) load_kv_tile(stg1, Kp, Vp, bh, 1, tid);
    CP_COMMIT();

    float o[2][16][4];
#pragma unroll
    for (int m = 0; m < 2; m++)
#pragma unroll
        for (int i = 0; i < 16; i++)
#pragma unroll
            for (int j = 0; j < 4; j++) o[m][i][j] = 0.f;
    float mx[2][2], lx[2][2];
#pragma unroll
    for (int m = 0; m < 2; m++) { mx[m][0] = mx[m][1] = -1e30f; lx[m][0] = lx[m][1] = 0.f; }

    const int lrow = lane & 15;
    const int lcol = (lane >> 4) * 16;
    // Q smem ldsm base per m-frag
    const uint32_t qb0 = smb + (uint32_t)((wid * 32 + lrow) * AT_STRIDE + lcol);
    const uint32_t qb1 = smb + (uint32_t)((wid * 32 + 16 + lrow) * AT_STRIDE + lcol);

    for (int kt = 0; kt <= ktmax; kt++) {
        CP_WAIT1();
        __syncthreads();
        const uint32_t stg = (kt & 1) ? stg1 : stg0;
        const bool active = (kt * 64 <= row0 + 31);

        if (active) {
            // ---- S = Q K^T : s[m][nt][4], 6 LDSM -> 16 MMA per ks ----
            float s[2][8][4];
#pragma unroll
            for (int m = 0; m < 2; m++)
#pragma unroll
                for (int i = 0; i < 8; i++)
#pragma unroll
                    for (int j = 0; j < 4; j++) s[m][i][j] = 0.f;

#pragma unroll
            for (int ks = 0; ks < 8; ks++) {
                uint32_t a0[4], a1[4];
                LDSM_X4(a0[0], a0[1], a0[2], a0[3], qb0 + (uint32_t)(ks * 32));
                LDSM_X4(a1[0], a1[1], a1[2], a1[3], qb1 + (uint32_t)(ks * 32));
                uint32_t b[8][2];
#pragma unroll
                for (int nb = 0; nb < 4; nb++) {
                    uint32_t r0, r1, r2, r3;
                    uint32_t addr = stg +
                        (uint32_t)((nb * 16 + lrow) * AT_STRIDE + ks * 32 + lcol);
                    LDSM_X4(r0, r1, r2, r3, addr);
                    b[2 * nb][0] = r0; b[2 * nb][1] = r2;
                    b[2 * nb + 1][0] = r1; b[2 * nb + 1][1] = r3;
                }
#pragma unroll
                for (int nt = 0; nt < 8; nt++) MMAH(s[0][nt], a0, b[nt]);
#pragma unroll
                for (int nt = 0; nt < 8; nt++) MMAH(s[1][nt], a1, b[nt]);
            }

            // ---- causal mask ----
            if (kt * 64 + 63 > row0) {
                const int kb = kt * 64;
#pragma unroll
                for (int m = 0; m < 2; m++) {
#pragma unroll
                    for (int nt = 0; nt < 8; nt++) {
#pragma unroll
                        for (int e = 0; e < 4; e++) {
                            int col = kb + nt * 8 + gcol2 + (e & 1);
                            int row = row0 + m * 16 + grow + ((e >> 1) << 3);
                            if (col > row) s[m][nt][e] = -1e30f;
                        }
                    }
                }
            }

            // ---- online softmax (log2 domain) + rescale + pack + PV ----
            uint32_t pa[2][4][4];
#pragma unroll
            for (int m = 0; m < 2; m++) {
                float ml0 = -1e30f, ml1 = -1e30f;
#pragma unroll
                for (int nt = 0; nt < 8; nt++) {
                    ml0 = fmaxf(ml0, fmaxf(s[m][nt][0], s[m][nt][1]));
                    ml1 = fmaxf(ml1, fmaxf(s[m][nt][2], s[m][nt][3]));
                }
#pragma unroll
                for (int d = 1; d < 4; d <<= 1) {
                    ml0 = fmaxf(ml0, __shfl_xor_sync(0xFFFFFFFFu, ml0, d));
                    ml1 = fmaxf(ml1, __shfl_xor_sync(0xFFFFFFFFu, ml1, d));
                }
                float mn0 = fmaxf(mx[m][0], ml0), mn1 = fmaxf(mx[m][1], ml1);
                float sc0 = ex2f(mx[m][0] - mn0), sc1 = ex2f(mx[m][1] - mn1);
                float sum0 = 0.f, sum1 = 0.f;
#pragma unroll
                for (int nt = 0; nt < 8; nt++) {
                    s[m][nt][0] = ex2f(s[m][nt][0] - mn0);
                    s[m][nt][1] = ex2f(s[m][nt][1] - mn0);
                    s[m][nt][2] = ex2f(s[m][nt][2] - mn1);
                    s[m][nt][3] = ex2f(s[m][nt][3] - mn1);
                    sum0 += s[m][nt][0] + s[m][nt][1];
                    sum1 += s[m][nt][2] + s[m][nt][3];
                }
#pragma unroll
                for (int d = 1; d < 4; d <<= 1) {
                    sum0 += __shfl_xor_sync(0xFFFFFFFFu, sum0, d);
                    sum1 += __shfl_xor_sync(0xFFFFFFFFu, sum1, d);
                }
                lx[m][0] = lx[m][0] * sc0 + sum0;
                lx[m][1] = lx[m][1] * sc1 + sum1;
                mx[m][0] = mn0; mx[m][1] = mn1;
#pragma unroll
                for (int nt = 0; nt < 16; nt++) {
                    o[m][nt][0] *= sc0; o[m][nt][1] *= sc0;
                    o[m][nt][2] *= sc1; o[m][nt][3] *= sc1;
                }
#pragma unroll
                for (int j = 0; j < 4; j++) {
                    pa[m][j][0] = pack_h2(s[m][2*j][0],   s[m][2*j][1]);
                    pa[m][j][1] = pack_h2(s[m][2*j][2],   s[m][2*j][3]);
                    pa[m][j][2] = pack_h2(s[m][2*j+1][0], s[m][2*j+1][1]);
                    pa[m][j][3] = pack_h2(s[m][2*j+1][2], s[m][2*j+1][3]);
                }
            }

            // ---- O += P V : V frags shared across both m-frags ----
#pragma unroll
            for (int ks4 = 0; ks4 < 4; ks4++) {
#pragma unroll
                for (int np = 0; np < 8; np++) {
                    uint32_t r0, r1, r2, r3;
                    uint32_t addr = stg + V_OFF +
                        (uint32_t)((ks4 * 16 + lrow) * AT_STRIDE + np * 32 + lcol);
                    LDSM_X4_T(r0, r1, r2, r3, addr);
                    uint32_t b0[2] = { r0, r1 }, b1[2] = { r2, r3 };
                    MMAH(o[0][2 * np],     pa[0][ks4], b0);
                    MMAH(o[0][2 * np + 1], pa[0][ks4], b1);
                    MMAH(o[1][2 * np],     pa[1][ks4], b0);
                    MMAH(o[1][2 * np + 1], pa[1][ks4], b1);
                }
            }
        }

        __syncthreads();               // compute done before stage reuse
        if (kt + 2 <= ktmax)
            load_kv_tile((kt & 1) ? stg1 : stg0, Kp, Vp, bh, kt + 2, tid);
        CP_COMMIT();
    }

    // ---- epilogue: write fp16 directly into proj-GEMM A buffer ----
    const int b = bh >> 4, h = bh & 15;
#pragma unroll
    for (int m = 0; m < 2; m++) {
        float inv0 = 1.f / lx[m][0], inv1 = 1.f / lx[m][1];
        int r0 = row0 + m * 16 + grow;
#pragma unroll
        for (int nt = 0; nt < 16; nt++) {
            int col = h * HD_ + nt * 8 + gcol2;
            __half* p0 = Oa + ((size_t)(b * S_ + r0)) * D_ + col;
            __half* p1 = Oa + ((size_t)(b * S_ + r0 + 8)) * D_ + col;
            *(uint32_t*)p0 = pack_h2(o[m][nt][0] * inv0, o[m][nt][1] * inv0);
            *(uint32_t*)p1 = pack_h2(o[m][nt][2] * inv1, o[m][nt][3] * inv1);
        }
    }
}

// ---------------- launch ----------------
extern "C" void kernel_launch(void* const* d_in, const int* in_sizes, int n_in,
                              void* d_out, int out_size)
{
    const float* x     = (const float*)d_in[0];
    // d_in[1] = mask (causal tril, handled analytically)
    const float* sinp  = (const float*)d_in[2];
    const float* cosp  = (const float*)d_in[3];
    const float* Wqkv  = (const float*)d_in[4];
    const float* Wproj = (const float*)d_in[5];
    float* out = (float*)d_out;

    __half *a16, *b16, *q16, *k16, *v16;
    cudaGetSymbolAddress((void**)&a16, g_a16);
    cudaGetSymbolAddress((void**)&b16, g_b16);
    cudaGetSymbolAddress((void**)&q16, g_q16);
    cudaGetSymbolAddress((void**)&k16, g_k16);
    cudaGetSymbolAddress((void**)&v16, g_v16);

    cudaFuncSetAttribute(gemm_h,   cudaFuncAttributeMaxDynamicSharedMemorySize, GEMM_SMEM);
    cudaFuncSetAttribute(gemm_qkv, cudaFuncAttributeMaxDynamicSharedMemorySize, GEMM_SMEM);
    cudaFuncSetAttribute(attn_h,   cudaFuncAttributeMaxDynamicSharedMemorySize, ATTN_SMEM);

    // 1) convert x and Wqkv to fp16
    conv16<<<(M_ * K_ / 4 + 255) / 256, 256>>>(x, a16, M_ * K_ / 4);
    conv_w_t16<<<dim3(N3_ / 32, K_ / 32), 256>>>(Wqkv, b16, K_, N3_);

    // 2) QKV projection + fused RoPE + head-major fp16 scatter
    gemm_qkv<<<dim3(N3_ / 256, M_ / 128), 512, GEMM_SMEM>>>(a16, b16, sinp, cosp,
                                                            q16, k16, v16);

    // 3) causal flash attention (tensor cores); writes proj A operand fp16
    attn_h<<<dim3(S_ / 128, B_ * H_), 128, ATTN_SMEM>>>(q16, k16, v16, a16);

    // 4) output projection (tensor cores)
    conv_w_t16<<<dim3(D_ / 32, K_ / 32), 256>>>(Wproj, b16, K_, D_);
    gemm_h<<<dim3(D_ / 256, M_ / 128), 512, GEMM_SMEM>>>(a16, b16, out, D_, K_);
}